// round 8
// baseline (speedup 1.0000x reference)
#include <cuda_runtime.h>
#include <cuda_fp16.h>
#include <cstdint>

// ============================================================================
// Problem constants
// ============================================================================
#define NFEAT 4096
#define MROWS 1024
#define KTOP  41.0f
#define WSCALE 4096.0f          // 2^12, exact power of two
#define INV_WSCALE (1.0f/4096.0f)

// Scratch (device globals — allocation-free rule)
__device__ float g_alpha_topk[NFEAT];
__device__ __align__(128) __half g_Wh[(size_t)NFEAT * NFEAT];   // W * 2^12, fp16
__device__ __align__(128) __half g_Xh[(size_t)MROWS * NFEAT];   // x, fp16
__device__ int g_coldone[32];                                   // W K-column flags

// ============================================================================
// Small PTX helpers (base-arch safe: sm_80+ features only)
// ============================================================================
__device__ __forceinline__ uint32_t smem_to_u32(const void* p) {
    uint32_t a;
    asm("{ .reg .u64 t; cvta.to.shared.u64 t, %1; cvt.u32.u64 %0, t; }" : "=r"(a) : "l"(p));
    return a;
}
__device__ __forceinline__ void cp16(uint32_t dst_smem, const void* src) {
    asm volatile("cp.async.cg.shared.global [%0], [%1], 16;" :: "r"(dst_smem), "l"(src) : "memory");
}
#define CP_COMMIT() asm volatile("cp.async.commit_group;" ::: "memory")
#define CP_WAIT1()  asm volatile("cp.async.wait_group 1;"  ::: "memory")

__device__ __forceinline__ void mma16816(float* c, const uint32_t* a, const uint32_t* b) {
    asm volatile(
        "mma.sync.aligned.m16n8k16.row.col.f32.f16.f16.f32 "
        "{%0,%1,%2,%3}, {%4,%5,%6,%7}, {%8,%9}, {%0,%1,%2,%3};"
        : "+f"(c[0]), "+f"(c[1]), "+f"(c[2]), "+f"(c[3])
        : "r"(a[0]), "r"(a[1]), "r"(a[2]), "r"(a[3]), "r"(b[0]), "r"(b[1]));
}
__device__ __forceinline__ void ldmx4(uint32_t* r, uint32_t addr) {
    asm volatile("ldmatrix.sync.aligned.m8n8.x4.shared.b16 {%0,%1,%2,%3}, [%4];"
                 : "=r"(r[0]), "=r"(r[1]), "=r"(r[2]), "=r"(r[3]) : "r"(addr));
}

// Consumer-side wait: column col of Wh complete (64 tiles).
__device__ __forceinline__ void wait_col(int col) {
    volatile int* f = &g_coldone[col];
    if (*f < 64) {
        while (*f < 64) __nanosleep(256);
        __threadfence();   // acquire on the slow path
    }
}

// ============================================================================
// Kernel 1 (prep): blocks 0..1023 convert x->fp16 (full-chip streaming);
// block 1024 resets flags and runs the collapsed Dykstra soft-top-k.
// ============================================================================
__global__ void prep_kernel(const float* __restrict__ alpha, const float* __restrict__ X) {
    if (blockIdx.x < 1024) {
        const int blk = blockIdx.x * 4096;
        const int t4  = threadIdx.x * 4;
#pragma unroll
        for (int q = 0; q < 4; q++) {
            int i = blk + q * 1024 + t4;
            float4 v = *reinterpret_cast<const float4*>(X + i);
            __half2 h0 = __floats2half2_rn(v.x, v.y);
            __half2 h1 = __floats2half2_rn(v.z, v.w);
            uint2 packed;
            packed.x = *reinterpret_cast<uint32_t*>(&h0);
            packed.y = *reinterpret_cast<uint32_t*>(&h1);
            *reinterpret_cast<uint2*>(&g_Xh[i]) = packed;
        }
        return;
    }

    const int tid  = threadIdx.x;
    if (tid < 32) g_coldone[tid] = 0;        // reset flags each launch/replay
    const int wid  = tid >> 5;
    const int lane = tid & 31;
    float y0[16];
#pragma unroll
    for (int j = 0; j < 16; j++) y0[j] = alpha[tid + j * 256] * 100.0f;  // /0.01

    __shared__ float wsum[2][8];
    float S = 0.f;

    for (int it = 0; it < 50; it++) {
        float local = 0.f;
#pragma unroll
        for (int j = 0; j < 16; j++) local += __saturatef(y0[j] + S);
#pragma unroll
        for (int o = 16; o > 0; o >>= 1) local += __shfl_xor_sync(0xffffffffu, local, o);
        if (lane == 0) wsum[it & 1][wid] = local;
        __syncthreads();
        float f = 0.f;
#pragma unroll
        for (int w = 0; w < 8; w++) f += wsum[it & 1][w];
        float dS = (KTOP - f) / (float)NFEAT;
        S += dS;
        if (fabsf(dS) < 1e-9f) break;        // uniform branch
    }
#pragma unroll
    for (int j = 0; j < 16; j++)
        g_alpha_topk[tid + j * 256] = __saturatef(y0[j] + S);
}

// ============================================================================
// Kernel 2 (fused): grid = 40 builder CTAs (bid<40) + 256 GEMM CTAs.
// 296 blocks == exactly 2 CTAs/SM * 148 SMs => all co-resident; builders are
// low block-ids (wave-1), GEMM CTAs only ever wait on builders => deadlock-free.
//
// Builders: W tiles in column-major order (col = 128-wide K-slab of Wh).
//   Tile = V[i0:i0+64, c0:c0+128] -> Wh diagonals. Double-buffered cp.async of
//   raw fp32 V overlaps the previous tile's scale+convert+STG phase.
// GEMM: identical to R7 (warp tile 64x64, 3-stage cp.async, ldmatrix.x4,
//   interleaved issue), plus a per-stage wait on the producing column flag.
// ============================================================================
#define NBUILD 40
#define BTI 64
#define BTC 128
#define BSTR 132                        // fp32 smem stride (16B-aligned rows)
#define BBUF (BTI * BSTR)               // 8448 floats

#define BM 128
#define BN 128
#define NS (NFEAT / 64)                 // 64 K-stages
#define STAGE_A 16384                   // 128 rows x 128 B
#define STAGE_BYTES 32768
#define GEMM_SMEM (3 * STAGE_BYTES)     // 98304 B (builder needs 68KB of it)

__device__ __forceinline__ void issue_A(int s, uint32_t sb, int m0, int tid) {
    if (s < NS) {
        wait_col(s >> 1);               // Wh K-columns are 128 wide = 2 stages
        const int buf = s % 3;
        const int k0h = s * 64;
#pragma unroll
        for (int p = 0; p < 8; p++) {
            int idx = tid + p * 128;
            int row = idx >> 3, j = idx & 7;
            uint32_t off = (uint32_t)(row * 128 + j * 16);
            uint32_t sw  = off ^ (uint32_t)((row & 7) << 4);
            cp16(sb + buf * STAGE_BYTES + sw,
                 g_Xh + (size_t)(m0 + row) * NFEAT + k0h + j * 8);
        }
    }
}
__device__ __forceinline__ void issue_B(int s, uint32_t sb, int n0, int tid) {
    if (s < NS) {
        const int buf = s % 3;
        const int k0h = s * 64;
#pragma unroll
        for (int p = 0; p < 8; p++) {
            int idx = tid + p * 128;
            int row = idx >> 3, j = idx & 7;
            uint32_t off = (uint32_t)(row * 128 + j * 16);
            uint32_t sw  = off ^ (uint32_t)((row & 7) << 4);
            cp16(sb + buf * STAGE_BYTES + STAGE_A + sw,
                 g_Wh + (size_t)(n0 + row) * NFEAT + k0h + j * 8);
        }
    }
}

__device__ __forceinline__ void builder_issue_tile(int t, int pb, uint32_t sb,
                                                   const float* V, int tid) {
    if (t < 2048) {
        const int i0 = (t & 63) * 64;
        const int c0 = (t >> 6) * 128;
#pragma unroll
        for (int p = 0; p < 16; p++) {
            int idx = tid + p * 128;     // 0..2047
            int il  = idx >> 5;          // 0..63
            int jq  = idx & 31;          // float4 idx
            cp16(sb + (uint32_t)((pb * BBUF + il * BSTR + jq * 4) * 4),
                 V + (size_t)(i0 + il) * NFEAT + c0 + jq * 4);
        }
    }
}

__global__ __launch_bounds__(128, 2)
void fused_kernel(const float* __restrict__ V, float* __restrict__ OUT) {
    extern __shared__ char smem[];
    const uint32_t sb = smem_to_u32(smem);
    const int tid = threadIdx.x;

    if (blockIdx.x < NBUILD) {
        // ===================== builder =====================
        const int b = blockIdx.x;
        float* bufs = reinterpret_cast<float*>(smem);
        float* a_s  = bufs + 2 * BBUF;   // 64 floats

        builder_issue_tile(b, 0, sb, V, tid);
        CP_COMMIT();
        int pb = 0;
        for (int t = b; t < 2048; t += NBUILD) {
            builder_issue_tile(t + NBUILD, pb ^ 1, sb, V, tid);
            if (tid < 64) a_s[tid] = g_alpha_topk[(t & 63) * 64 + tid] * WSCALE;
            CP_COMMIT();
            CP_WAIT1();                  // tile t's data resident
            __syncthreads();

            const int i0 = (t & 63) * 64;
            const int c0 = (t >> 6) * 128;
            const float* buf = bufs + pb * BBUF;
            // 191 diagonals x <=33 even-aligned pairs
            for (int u = tid; u < 191 * 33; u += 128) {
                int d = u / 33;
                int j = u - d * 33;
                int ccLo = max(0, d - (BTI - 1));
                int ccHi = min(BTC - 1, d);
                int cc = (ccLo & ~1) + 2 * j;
                if (cc <= ccHi) {
                    bool v0 = (cc >= ccLo);
                    bool v1 = (cc + 1 <= ccHi);
                    int i0a = v0 ? (d - cc) : 0;
                    int i1a = v1 ? (d - cc - 1) : 0;
                    float f0 = v0 ? a_s[i0a] * buf[i0a * BSTR + cc] : 0.f;
                    float f1 = v1 ? a_s[i1a] * buf[i1a * BSTR + cc + 1] : 0.f;
                    int r = (i0 + c0 + d) & (NFEAT - 1);
                    size_t o = (size_t)r * NFEAT + c0 + cc;
                    if (v0 && v1) {
                        __half2 h = __floats2half2_rn(f0, f1);
                        *reinterpret_cast<__half2*>(&g_Wh[o]) = h;
                    } else if (v0) {
                        g_Wh[o] = __float2half_rn(f0);
                    } else {
                        g_Wh[o + 1] = __float2half_rn(f1);
                    }
                }
            }
            __threadfence();             // release Wh stores
            __syncthreads();
            if (tid == 0) atomicAdd(&g_coldone[t >> 6], 1);
            pb ^= 1;
        }
        return;
    }

    // ===================== GEMM =====================
    const int bid2 = blockIdx.x - NBUILD;
    const int wid  = tid >> 5;
    const int lane = tid & 31;
    const int wm   = wid >> 1;
    const int wn   = wid & 1;
    const int m0 = (bid2 >> 5) * BM;
    const int n0 = (bid2 & 31) * BN;

    float acc[32][4];
#pragma unroll
    for (int i = 0; i < 32; i++)
        acc[i][0] = acc[i][1] = acc[i][2] = acc[i][3] = 0.f;

    const int rowin = lane & 7;
    const int mat   = lane >> 3;
    const int rA = rowin + (mat & 1) * 8;
    const int cA = (mat >> 1) * 16;
    const int rB = rowin + (mat >> 1) * 8;
    const int cB = (mat & 1) * 16;

    uint32_t arow[4], brow[4], koffA[4], koffB[4];
#pragma unroll
    for (int mi = 0; mi < 4; mi++)
        arow[mi] = (uint32_t)((wm * 64 + mi * 16 + rA) * 128);
#pragma unroll
    for (int pr = 0; pr < 4; pr++)
        brow[pr] = (uint32_t)((wn * 64 + pr * 16 + rB) * 128) + STAGE_A;
#pragma unroll
    for (int ks = 0; ks < 4; ks++) {
        koffA[ks] = (uint32_t)((ks * 32 + cA) ^ (rowin << 4));
        koffB[ks] = (uint32_t)((ks * 32 + cB) ^ (rowin << 4));
    }

    issue_A(0, sb, m0, tid); issue_B(0, sb, n0, tid); CP_COMMIT();
    issue_A(1, sb, m0, tid); issue_B(1, sb, n0, tid); CP_COMMIT();

    for (int s = 0; s < NS; s++) {
        CP_WAIT1();
        __syncthreads();
        const uint32_t stg = sb + (uint32_t)((s % 3) * STAGE_BYTES);
#pragma unroll
        for (int ks = 0; ks < 4; ks++) {
            uint32_t af[4][4], bf[8][2];
#pragma unroll
            for (int mi = 0; mi < 4; mi++)
                ldmx4(af[mi], stg + arow[mi] + koffA[ks]);
#pragma unroll
            for (int pr = 0; pr < 4; pr++) {
                uint32_t r[4];
                ldmx4(r, stg + brow[pr] + koffB[ks]);
                bf[pr * 2][0]     = r[0];
                bf[pr * 2][1]     = r[1];
                bf[pr * 2 + 1][0] = r[2];
                bf[pr * 2 + 1][1] = r[3];
            }
            if (ks == 0) issue_A(s + 2, sb, m0, tid);
            if (ks == 1) { issue_B(s + 2, sb, n0, tid); CP_COMMIT(); }
#pragma unroll
            for (int mi = 0; mi < 4; mi++)
#pragma unroll
                for (int ni = 0; ni < 8; ni++)
                    mma16816(acc[mi * 8 + ni], af[mi], bf[ni]);
        }
    }

    // Epilogue: undo 2^12 W scaling.
    const int t4 = lane >> 2, tq = lane & 3;
#pragma unroll
    for (int mi = 0; mi < 4; mi++) {
        int r = m0 + wm * 64 + mi * 16 + t4;
#pragma unroll
        for (int ni = 0; ni < 8; ni++) {
            int c = n0 + wn * 64 + ni * 8 + tq * 2;
            float* a = acc[mi * 8 + ni];
            float2 v0 = make_float2(a[0] * INV_WSCALE, a[1] * INV_WSCALE);
            float2 v1 = make_float2(a[2] * INV_WSCALE, a[3] * INV_WSCALE);
            *reinterpret_cast<float2*>(OUT + (size_t)r * NFEAT + c) = v0;
            *reinterpret_cast<float2*>(OUT + (size_t)(r + 8) * NFEAT + c) = v1;
        }
    }
}

// ============================================================================
// Launch
// ============================================================================
extern "C" void kernel_launch(void* const* d_in, const int* in_sizes, int n_in,
                              void* d_out, int out_size) {
    const float* x = nullptr;
    const float* V = nullptr;
    const float* alpha = nullptr;
    for (int i = 0; i < n_in; i++) {
        if (in_sizes[i] == NFEAT)               alpha = (const float*)d_in[i];
        else if (in_sizes[i] == MROWS * NFEAT)  x     = (const float*)d_in[i];
        else                                    V     = (const float*)d_in[i];
    }
    float* out = (float*)d_out;

    cudaFuncSetAttribute(fused_kernel, cudaFuncAttributeMaxDynamicSharedMemorySize, GEMM_SMEM);

    prep_kernel<<<1025, 256>>>(alpha, x);
    fused_kernel<<<NBUILD + 256, 128, GEMM_SMEM>>>(V, out);
}

// round 9
// speedup vs baseline: 2.6682x; 2.6682x over previous
#include <cuda_runtime.h>
#include <cuda_fp16.h>
#include <cstdint>

// ============================================================================
// Problem constants
// ============================================================================
#define NFEAT 4096
#define MROWS 1024
#define KTOP  41.0f
#define WSCALE 4096.0f          // 2^12, exact power of two
#define INV_WSCALE (1.0f/4096.0f)

// Scratch (device globals — allocation-free rule)
__device__ float g_alpha_topk[NFEAT];
__device__ __align__(128) __half g_Wh[(size_t)NFEAT * NFEAT];   // W * 2^12, fp16
__device__ __align__(128) __half g_Xh[(size_t)MROWS * NFEAT];   // x, fp16
__device__ int g_coldone[32];                                   // Wh K-column flags

// ============================================================================
// Small PTX helpers (base-arch safe: sm_80+/sm_90 features only)
// ============================================================================
__device__ __forceinline__ uint32_t smem_to_u32(const void* p) {
    uint32_t a;
    asm("{ .reg .u64 t; cvta.to.shared.u64 t, %1; cvt.u32.u64 %0, t; }" : "=r"(a) : "l"(p));
    return a;
}
__device__ __forceinline__ void cp16(uint32_t dst_smem, const void* src) {
    asm volatile("cp.async.cg.shared.global [%0], [%1], 16;" :: "r"(dst_smem), "l"(src) : "memory");
}
#define CP_COMMIT() asm volatile("cp.async.commit_group;" ::: "memory")
#define CP_WAIT1()  asm volatile("cp.async.wait_group 1;"  ::: "memory")

__device__ __forceinline__ void mma16816(float* c, const uint32_t* a, const uint32_t* b) {
    asm volatile(
        "mma.sync.aligned.m16n8k16.row.col.f32.f16.f16.f32 "
        "{%0,%1,%2,%3}, {%4,%5,%6,%7}, {%8,%9}, {%0,%1,%2,%3};"
        : "+f"(c[0]), "+f"(c[1]), "+f"(c[2]), "+f"(c[3])
        : "r"(a[0]), "r"(a[1]), "r"(a[2]), "r"(a[3]), "r"(b[0]), "r"(b[1]));
}
__device__ __forceinline__ void ldmx4(uint32_t* r, uint32_t addr) {
    asm volatile("ldmatrix.sync.aligned.m8n8.x4.shared.b16 {%0,%1,%2,%3}, [%4];"
                 : "=r"(r[0]), "=r"(r[1]), "=r"(r[2]), "=r"(r[3]) : "r"(addr));
}

// Consumer wait: Wh K-column col complete (64 producer tiles). Fast path is a
// single L2 load; producer did __threadfence before atomicAdd, and all our
// consumer reads of Wh go through cp.async.cg (L2 path) => coherent.
__device__ __forceinline__ void wait_col(int col) {
    volatile int* f = &g_coldone[col];
    if (*f < 64) {
        while (*f < 64) __nanosleep(128);
        __threadfence();
    }
}

// ============================================================================
// Kernel 1 (prep): blocks 0..1023 convert x->fp16; block 1024 resets column
// flags and runs the collapsed Dykstra soft-top-k (early-break ~iter 8-10).
// Fully precedes build_w in stream order => Xh and flags are safe for the
// PDL-overlapped GEMM.
// ============================================================================
__global__ void prep_kernel(const float* __restrict__ alpha, const float* __restrict__ X) {
    if (blockIdx.x < 1024) {
        const int blk = blockIdx.x * 4096;
        const int t4  = threadIdx.x * 4;
#pragma unroll
        for (int q = 0; q < 4; q++) {
            int i = blk + q * 1024 + t4;
            float4 v = *reinterpret_cast<const float4*>(X + i);
            __half2 h0 = __floats2half2_rn(v.x, v.y);
            __half2 h1 = __floats2half2_rn(v.z, v.w);
            uint2 packed;
            packed.x = *reinterpret_cast<uint32_t*>(&h0);
            packed.y = *reinterpret_cast<uint32_t*>(&h1);
            *reinterpret_cast<uint2*>(&g_Xh[i]) = packed;
        }
        return;
    }

    const int tid  = threadIdx.x;
    if (tid < 32) g_coldone[tid] = 0;        // reset per launch/replay
    const int wid  = tid >> 5;
    const int lane = tid & 31;
    float y0[16];
#pragma unroll
    for (int j = 0; j < 16; j++) y0[j] = alpha[tid + j * 256] * 100.0f;  // /0.01

    __shared__ float wsum[2][8];
    float S = 0.f;

    for (int it = 0; it < 50; it++) {
        float local = 0.f;
#pragma unroll
        for (int j = 0; j < 16; j++) local += __saturatef(y0[j] + S);
#pragma unroll
        for (int o = 16; o > 0; o >>= 1) local += __shfl_xor_sync(0xffffffffu, local, o);
        if (lane == 0) wsum[it & 1][wid] = local;
        __syncthreads();
        float f = 0.f;
#pragma unroll
        for (int w = 0; w < 8; w++) f += wsum[it & 1][w];
        float dS = (KTOP - f) / (float)NFEAT;
        S += dS;
        if (fabsf(dS) < 1e-9f) break;        // uniform branch
    }
#pragma unroll
    for (int j = 0; j < 16; j++)
        g_alpha_topk[tid + j * 256] = __saturatef(y0[j] + S);
}

// ============================================================================
// Kernel 2: Wh[r,c] = 2^12*a[i]*V[i,c], r=(i+c)%n. Full-chip (2048 blocks,
// 256 threads), fp16 smem diagonal transpose, COLUMN-MAJOR tile order so low
// block ids complete K-column 0 first. Each block triggers the dependent GEMM
// launch at start (PDL) and publishes its tile via fence+atomicAdd at end.
// ============================================================================
#define TI 64
#define TC 128
#define STRH 136   // smem stride in halves; diag lane stride odd => conflict-free

__global__ __launch_bounds__(256) void build_w_kernel(const float* __restrict__ V) {
    cudaTriggerProgrammaticLaunchCompletion();
    __shared__ __half tile[TI * STRH];
    const int b   = blockIdx.x;
    const int tid = threadIdx.x;
    const int c_blk = b >> 6;            // 0..31  (column-major: col varies slowest)
    const int i0 = (b & 63) * TI;
    const int c0 = c_blk * TC;

    // Load V[i0:i0+64, c0:c0+128] (float4, coalesced), scale, cvt fp16, STS.64.
#pragma unroll
    for (int pp = 0; pp < 8; pp++) {
        int idx = tid + pp * 256;        // 0..2047
        int il  = idx >> 5;              // 0..63
        int jq  = idx & 31;              // float4 index
        float a = g_alpha_topk[i0 + il] * WSCALE;
        float4 v = *reinterpret_cast<const float4*>(V + (size_t)(i0 + il) * NFEAT + c0 + jq * 4);
        __half2 h0 = __floats2half2_rn(a * v.x, a * v.y);
        __half2 h1 = __floats2half2_rn(a * v.z, a * v.w);
        uint2 packed;
        packed.x = *reinterpret_cast<uint32_t*>(&h0);
        packed.y = *reinterpret_cast<uint32_t*>(&h1);
        *reinterpret_cast<uint2*>(&tile[il * STRH + jq * 4]) = packed;
    }
    __syncthreads();

    // Store by W-row diagonal d = r - (i0+c0); paired half2 STG, even-aligned.
    const int row7 = tid / 36;           // 0..7 (7 invalid)
    const int p    = tid % 36;
    for (int base = 0; base < TI + TC - 1; base += 7) {
        int d = base + row7;
        if (row7 < 7 && d < TI + TC - 1) {
            int ccLo = max(0, d - (TI - 1));
            int ccHi = min(TC - 1, d);
            int cc = (ccLo & ~1) + 2 * p;
            if (cc <= ccHi) {
                bool v0 = (cc >= ccLo);
                bool v1 = (cc + 1 <= ccHi);
                int idx0 = v0 ? ((d - cc) * STRH + cc) : 0;
                int idx1 = v1 ? ((d - cc - 1) * STRH + cc + 1) : 0;
                __half h0 = v0 ? tile[idx0] : __half(0);
                __half h1 = v1 ? tile[idx1] : __half(0);
                int r = (i0 + c0 + d) & (NFEAT - 1);
                size_t o = (size_t)r * NFEAT + c0 + cc;
                if (v0 && v1) {
                    __half2 h = __halves2half2(h0, h1);
                    *reinterpret_cast<__half2*>(&g_Wh[o]) = h;
                } else if (v0) {
                    g_Wh[o] = h0;
                } else {
                    g_Wh[o + 1] = h1;
                }
            }
        }
    }

    __threadfence();                     // make Wh stores L2-visible
    __syncthreads();
    if (tid == 0) atomicAdd(&g_coldone[c_blk], 1);
}

// ============================================================================
// Kernel 3: fp16 GEMM  out[1024,4096] = (Xh @ Wh^T) * 2^-12, fp32 accumulate.
//   Launched with programmatic stream serialization (PDL): may start while
//   build_w's last wave runs; per-stage A-issue gates on the column flag.
//   128 threads (4 warps, 2x2), warp tile 64x64, BM=BN=128, BK=64 halves,
//   3-stage cp.async pipeline with interleaved issue, ldmatrix.x4, 2 CTAs/SM.
// ============================================================================
#define BM 128
#define BN 128
#define NS (NFEAT / 64)                 // 64 K-stages
#define STAGE_A 16384                   // 128 rows x 128 B
#define STAGE_BYTES 32768
#define GEMM_SMEM (3 * STAGE_BYTES)     // 98304 B

__device__ __forceinline__ void issue_A(int s, uint32_t sb, int m0, int tid) {
    if (s < NS) {
        wait_col(s >> 1);               // Wh K-columns are 128 wide = 2 stages
        const int buf = s % 3;
        const int k0h = s * 64;
#pragma unroll
        for (int p = 0; p < 8; p++) {
            int idx = tid + p * 128;
            int row = idx >> 3, j = idx & 7;
            uint32_t off = (uint32_t)(row * 128 + j * 16);
            uint32_t sw  = off ^ (uint32_t)((row & 7) << 4);
            cp16(sb + buf * STAGE_BYTES + sw,
                 g_Xh + (size_t)(m0 + row) * NFEAT + k0h + j * 8);
        }
    }
}
__device__ __forceinline__ void issue_B(int s, uint32_t sb, int n0, int tid) {
    if (s < NS) {
        const int buf = s % 3;
        const int k0h = s * 64;
#pragma unroll
        for (int p = 0; p < 8; p++) {
            int idx = tid + p * 128;
            int row = idx >> 3, j = idx & 7;
            uint32_t off = (uint32_t)(row * 128 + j * 16);
            uint32_t sw  = off ^ (uint32_t)((row & 7) << 4);
            cp16(sb + buf * STAGE_BYTES + STAGE_A + sw,
                 g_Wh + (size_t)(n0 + row) * NFEAT + k0h + j * 8);
        }
    }
}

__global__ __launch_bounds__(128, 2)
void gemm_kernel(float* __restrict__ OUT) {
    extern __shared__ char smem[];
    const uint32_t sb = smem_to_u32(smem);
    const int tid  = threadIdx.x;
    const int wid  = tid >> 5;
    const int lane = tid & 31;
    const int wm   = wid >> 1;
    const int wn   = wid & 1;
    const int m0 = blockIdx.y * BM;
    const int n0 = blockIdx.x * BN;

    float acc[32][4];
#pragma unroll
    for (int i = 0; i < 32; i++)
        acc[i][0] = acc[i][1] = acc[i][2] = acc[i][3] = 0.f;

    // ldmatrix per-lane addressing. lane = mat*8 + rowin.
    const int rowin = lane & 7;
    const int mat   = lane >> 3;
    const int rA = rowin + (mat & 1) * 8;
    const int cA = (mat >> 1) * 16;
    const int rB = rowin + (mat >> 1) * 8;
    const int cB = (mat & 1) * 16;

    uint32_t arow[4], brow[4], koffA[4], koffB[4];
#pragma unroll
    for (int mi = 0; mi < 4; mi++)
        arow[mi] = (uint32_t)((wm * 64 + mi * 16 + rA) * 128);
#pragma unroll
    for (int pr = 0; pr < 4; pr++)
        brow[pr] = (uint32_t)((wn * 64 + pr * 16 + rB) * 128) + STAGE_A;
#pragma unroll
    for (int ks = 0; ks < 4; ks++) {
        koffA[ks] = (uint32_t)((ks * 32 + cA) ^ (rowin << 4));
        koffB[ks] = (uint32_t)((ks * 32 + cB) ^ (rowin << 4));
    }

    issue_A(0, sb, m0, tid); issue_B(0, sb, n0, tid); CP_COMMIT();
    issue_A(1, sb, m0, tid); issue_B(1, sb, n0, tid); CP_COMMIT();

    for (int s = 0; s < NS; s++) {
        CP_WAIT1();
        __syncthreads();
        // Barrier proves mma(s-1) complete => buffer (s+2)%3 == (s-1)%3 safe.
        const uint32_t stg = sb + (uint32_t)((s % 3) * STAGE_BYTES);
#pragma unroll
        for (int ks = 0; ks < 4; ks++) {
            uint32_t af[4][4], bf[8][2];
#pragma unroll
            for (int mi = 0; mi < 4; mi++)
                ldmx4(af[mi], stg + arow[mi] + koffA[ks]);
#pragma unroll
            for (int pr = 0; pr < 4; pr++) {
                uint32_t r[4];
                ldmx4(r, stg + brow[pr] + koffB[ks]);
                bf[pr * 2][0]     = r[0];
                bf[pr * 2][1]     = r[1];
                bf[pr * 2 + 1][0] = r[2];
                bf[pr * 2 + 1][1] = r[3];
            }
            if (ks == 0) issue_A(s + 2, sb, m0, tid);
            if (ks == 1) { issue_B(s + 2, sb, n0, tid); CP_COMMIT(); }
#pragma unroll
            for (int mi = 0; mi < 4; mi++)
#pragma unroll
                for (int ni = 0; ni < 8; ni++)
                    mma16816(acc[mi * 8 + ni], af[mi], bf[ni]);
        }
    }

    // Epilogue: undo 2^12 W scaling.
    const int t4 = lane >> 2, tq = lane & 3;
#pragma unroll
    for (int mi = 0; mi < 4; mi++) {
        int r = m0 + wm * 64 + mi * 16 + t4;
#pragma unroll
        for (int ni = 0; ni < 8; ni++) {
            int c = n0 + wn * 64 + ni * 8 + tq * 2;
            float* a = acc[mi * 8 + ni];
            float2 v0 = make_float2(a[0] * INV_WSCALE, a[1] * INV_WSCALE);
            float2 v1 = make_float2(a[2] * INV_WSCALE, a[3] * INV_WSCALE);
            *reinterpret_cast<float2*>(OUT + (size_t)r * NFEAT + c) = v0;
            *reinterpret_cast<float2*>(OUT + (size_t)(r + 8) * NFEAT + c) = v1;
        }
    }
}

// ============================================================================
// Launch: prep -> build_w -> gemm, with the gemm launch carrying the
// programmatic-stream-serialization attribute so it overlaps build_w's tail.
// If the attribute is ignored, behavior degrades exactly to the serial R7
// schedule (flags are then always satisfied).
// ============================================================================
extern "C" void kernel_launch(void* const* d_in, const int* in_sizes, int n_in,
                              void* d_out, int out_size) {
    const float* x = nullptr;
    const float* V = nullptr;
    const float* alpha = nullptr;
    for (int i = 0; i < n_in; i++) {
        if (in_sizes[i] == NFEAT)               alpha = (const float*)d_in[i];
        else if (in_sizes[i] == MROWS * NFEAT)  x     = (const float*)d_in[i];
        else                                    V     = (const float*)d_in[i];
    }
    float* out = (float*)d_out;

    cudaFuncSetAttribute(gemm_kernel, cudaFuncAttributeMaxDynamicSharedMemorySize, GEMM_SMEM);

    prep_kernel<<<1025, 256>>>(alpha, x);
    build_w_kernel<<<2048, 256>>>(V);

    cudaLaunchConfig_t cfg = {};
    cfg.gridDim  = dim3(NFEAT / BN, MROWS / BM, 1);   // (32, 8)
    cfg.blockDim = dim3(128, 1, 1);
    cfg.dynamicSmemBytes = GEMM_SMEM;
    cfg.stream = 0;
    cudaLaunchAttribute attrs[1];
    attrs[0].id = cudaLaunchAttributeProgrammaticStreamSerialization;
    attrs[0].val.programmaticStreamSerializationAllowed = 1;
    cfg.attrs = attrs;
    cfg.numAttrs = 1;
    cudaLaunchKernelEx(&cfg, gemm_kernel, out);
}

// round 10
// speedup vs baseline: 2.7039x; 1.0134x over previous
#include <cuda_runtime.h>
#include <cuda_fp16.h>
#include <cstdint>

// ============================================================================
// Problem constants
// ============================================================================
#define NFEAT 4096
#define MROWS 1024
#define KTOP  41.0f
#define WSCALE 4096.0f          // 2^12, exact power of two
#define INV_WSCALE (1.0f/4096.0f)

// Scratch (device globals — allocation-free rule)
__device__ float g_alpha_topk[NFEAT];
__device__ __align__(128) __half g_Wh[(size_t)NFEAT * NFEAT];   // W * 2^12, fp16
__device__ __align__(128) __half g_Xh[(size_t)MROWS * NFEAT];   // x, fp16
__device__ int g_aflag;                                         // alpha-done flag

// ============================================================================
// Small PTX helpers (base-arch safe: sm_80+ features only)
// ============================================================================
__device__ __forceinline__ uint32_t smem_to_u32(const void* p) {
    uint32_t a;
    asm("{ .reg .u64 t; cvta.to.shared.u64 t, %1; cvt.u32.u64 %0, t; }" : "=r"(a) : "l"(p));
    return a;
}
__device__ __forceinline__ void cp16(uint32_t dst_smem, const void* src) {
    asm volatile("cp.async.cg.shared.global [%0], [%1], 16;" :: "r"(dst_smem), "l"(src) : "memory");
}
#define CP_COMMIT() asm volatile("cp.async.commit_group;" ::: "memory")
#define CP_WAIT1()  asm volatile("cp.async.wait_group 1;"  ::: "memory")

__device__ __forceinline__ void mma16816(float* c, const uint32_t* a, const uint32_t* b) {
    asm volatile(
        "mma.sync.aligned.m16n8k16.row.col.f32.f16.f16.f32 "
        "{%0,%1,%2,%3}, {%4,%5,%6,%7}, {%8,%9}, {%0,%1,%2,%3};"
        : "+f"(c[0]), "+f"(c[1]), "+f"(c[2]), "+f"(c[3])
        : "r"(a[0]), "r"(a[1]), "r"(a[2]), "r"(a[3]), "r"(b[0]), "r"(b[1]));
}
__device__ __forceinline__ void ldmx4(uint32_t* r, uint32_t addr) {
    asm volatile("ldmatrix.sync.aligned.m8n8.x4.shared.b16 {%0,%1,%2,%3}, [%4];"
                 : "=r"(r[0]), "=r"(r[1]), "=r"(r[2]), "=r"(r[3]) : "r"(addr));
}

// ============================================================================
// Kernel 1 (fully fused prep/build, 3073 blocks x 256 thr):
//   bid 0        : collapsed-Dykstra soft-top-k, then fence + set g_aflag.
//   bid 1..1024  : x -> fp16 (independent; fills wave 1 while alpha runs).
//   bid >= 1025  : W tile build — poll g_aflag (bid 0 is wave-1 => no
//                  deadlock), read alpha via __ldcg (L2, coherent past the
//                  producer fence), then R7's fp16 smem diagonal transpose.
// ============================================================================
#define TI 64
#define TC 128
#define STRH 136   // smem stride in halves; diag lane stride odd => conflict-free

__global__ __launch_bounds__(256) void prep_build_kernel(const float* __restrict__ alpha,
                                                         const float* __restrict__ X,
                                                         const float* __restrict__ V) {
    const int bid = blockIdx.x;
    const int tid = threadIdx.x;

    if (bid == 0) {
        // ---- soft-top-k: S' = S + (k - sum(clip(y0+S,0,1)))/n ----
        const int wid  = tid >> 5;
        const int lane = tid & 31;
        float y0[16];
#pragma unroll
        for (int j = 0; j < 16; j++) y0[j] = alpha[tid + j * 256] * 100.0f;  // /0.01

        __shared__ float wsum[2][8];
        float S = 0.f;
        for (int it = 0; it < 50; it++) {
            float local = 0.f;
#pragma unroll
            for (int j = 0; j < 16; j++) local += __saturatef(y0[j] + S);
#pragma unroll
            for (int o = 16; o > 0; o >>= 1) local += __shfl_xor_sync(0xffffffffu, local, o);
            if (lane == 0) wsum[it & 1][wid] = local;
            __syncthreads();
            float f = 0.f;
#pragma unroll
            for (int w = 0; w < 8; w++) f += wsum[it & 1][w];
            float dS = (KTOP - f) / (float)NFEAT;
            S += dS;
            if (fabsf(dS) < 1e-9f) break;        // uniform branch
        }
#pragma unroll
        for (int j = 0; j < 16; j++)
            g_alpha_topk[tid + j * 256] = __saturatef(y0[j] + S);
        __threadfence();                         // publish alpha to L2
        __syncthreads();
        if (tid == 0) atomicExch(&g_aflag, 1);
        return;
    }

    if (bid <= 1024) {
        // ---- x -> fp16 ----
        const int blk = (bid - 1) * 4096;
        const int t4  = tid * 4;
#pragma unroll
        for (int q = 0; q < 4; q++) {
            int i = blk + q * 1024 + t4;
            float4 v = *reinterpret_cast<const float4*>(X + i);
            __half2 h0 = __floats2half2_rn(v.x, v.y);
            __half2 h1 = __floats2half2_rn(v.z, v.w);
            uint2 packed;
            packed.x = *reinterpret_cast<uint32_t*>(&h0);
            packed.y = *reinterpret_cast<uint32_t*>(&h1);
            *reinterpret_cast<uint2*>(&g_Xh[i]) = packed;
        }
        return;
    }

    // ---- W tile build: Wh[r,c] = 2^12*a[i]*V[i,c], r=(i+c)%n ----
    __shared__ __half tile[TI * STRH];
    const int t  = bid - 1025;           // 0..2047
    const int i0 = (t & 63) * TI;
    const int c0 = (t >> 6) * TC;

    // Wait for alpha (one polling thread, then block-wide barrier).
    if (tid == 0) {
        volatile int* f = &g_aflag;
        while (*f == 0) __nanosleep(256);
    }
    __syncthreads();

    // Load V (float4, coalesced), scale by alpha (L2 read), cvt fp16, STS.64.
#pragma unroll
    for (int pp = 0; pp < 8; pp++) {
        int idx = tid + pp * 256;        // 0..2047
        int il  = idx >> 5;              // 0..63
        int jq  = idx & 31;              // float4 index
        float a = __ldcg(&g_alpha_topk[i0 + il]) * WSCALE;
        float4 v = *reinterpret_cast<const float4*>(V + (size_t)(i0 + il) * NFEAT + c0 + jq * 4);
        __half2 h0 = __floats2half2_rn(a * v.x, a * v.y);
        __half2 h1 = __floats2half2_rn(a * v.z, a * v.w);
        uint2 packed;
        packed.x = *reinterpret_cast<uint32_t*>(&h0);
        packed.y = *reinterpret_cast<uint32_t*>(&h1);
        *reinterpret_cast<uint2*>(&tile[il * STRH + jq * 4]) = packed;
    }
    __syncthreads();

    // Store by W-row diagonal d = r - (i0+c0); paired half2 STG, even-aligned.
    const int row7 = tid / 36;           // 0..7 (7 invalid)
    const int p    = tid % 36;
    for (int base = 0; base < TI + TC - 1; base += 7) {
        int d = base + row7;
        if (row7 < 7 && d < TI + TC - 1) {
            int ccLo = max(0, d - (TI - 1));
            int ccHi = min(TC - 1, d);
            int cc = (ccLo & ~1) + 2 * p;
            if (cc <= ccHi) {
                bool v0 = (cc >= ccLo);
                bool v1 = (cc + 1 <= ccHi);
                int idx0 = v0 ? ((d - cc) * STRH + cc) : 0;
                int idx1 = v1 ? ((d - cc - 1) * STRH + cc + 1) : 0;
                __half h0 = v0 ? tile[idx0] : __half(0);
                __half h1 = v1 ? tile[idx1] : __half(0);
                int r = (i0 + c0 + d) & (NFEAT - 1);
                size_t o = (size_t)r * NFEAT + c0 + cc;
                if (v0 && v1) {
                    __half2 h = __halves2half2(h0, h1);
                    *reinterpret_cast<__half2*>(&g_Wh[o]) = h;
                } else if (v0) {
                    g_Wh[o] = h0;
                } else {
                    g_Wh[o + 1] = h1;
                }
            }
        }
    }
}

// ============================================================================
// Kernel 2: fp16 GEMM  out[1024,4096] = (Xh @ Wh^T) * 2^-12, fp32 accumulate.
//   Identical to the R7 best: 128 threads (4 warps, 2x2), warp tile 64x64,
//   BM=BN=128, BK=64 halves, 3-stage cp.async pipeline with issue interleaved
//   into the ks loop, XOR-swizzled smem, ldmatrix.x4, 2 CTAs/SM.
//   Block (0,0) resets g_aflag for the next graph replay (build kernel fully
//   preceded us in stream order, so nobody still reads it).
// ============================================================================
#define BM 128
#define BN 128
#define NS (NFEAT / 64)                 // 64 K-stages
#define STAGE_A 16384                   // 128 rows x 128 B
#define STAGE_BYTES 32768
#define GEMM_SMEM (3 * STAGE_BYTES)     // 98304 B

__device__ __forceinline__ void issue_A(int s, uint32_t sb, int m0, int tid) {
    if (s < NS) {
        const int buf = s % 3;
        const int k0h = s * 64;
#pragma unroll
        for (int p = 0; p < 8; p++) {
            int idx = tid + p * 128;
            int row = idx >> 3, j = idx & 7;
            uint32_t off = (uint32_t)(row * 128 + j * 16);
            uint32_t sw  = off ^ (uint32_t)((row & 7) << 4);
            cp16(sb + buf * STAGE_BYTES + sw,
                 g_Xh + (size_t)(m0 + row) * NFEAT + k0h + j * 8);
        }
    }
}
__device__ __forceinline__ void issue_B(int s, uint32_t sb, int n0, int tid) {
    if (s < NS) {
        const int buf = s % 3;
        const int k0h = s * 64;
#pragma unroll
        for (int p = 0; p < 8; p++) {
            int idx = tid + p * 128;
            int row = idx >> 3, j = idx & 7;
            uint32_t off = (uint32_t)(row * 128 + j * 16);
            uint32_t sw  = off ^ (uint32_t)((row & 7) << 4);
            cp16(sb + buf * STAGE_BYTES + STAGE_A + sw,
                 g_Wh + (size_t)(n0 + row) * NFEAT + k0h + j * 8);
        }
    }
}

__global__ __launch_bounds__(128, 2)
void gemm_kernel(float* __restrict__ OUT) {
    extern __shared__ char smem[];
    const uint32_t sb = smem_to_u32(smem);
    const int tid  = threadIdx.x;
    if (blockIdx.x == 0 && blockIdx.y == 0 && tid == 0) g_aflag = 0;  // replay reset
    const int wid  = tid >> 5;
    const int lane = tid & 31;
    const int wm   = wid >> 1;
    const int wn   = wid & 1;
    const int m0 = blockIdx.y * BM;
    const int n0 = blockIdx.x * BN;

    float acc[32][4];
#pragma unroll
    for (int i = 0; i < 32; i++)
        acc[i][0] = acc[i][1] = acc[i][2] = acc[i][3] = 0.f;

    // ldmatrix per-lane addressing. lane = mat*8 + rowin.
    const int rowin = lane & 7;
    const int mat   = lane >> 3;
    const int rA = rowin + (mat & 1) * 8;
    const int cA = (mat >> 1) * 16;
    const int rB = rowin + (mat >> 1) * 8;
    const int cB = (mat & 1) * 16;

    uint32_t arow[4], brow[4], koffA[4], koffB[4];
#pragma unroll
    for (int mi = 0; mi < 4; mi++)
        arow[mi] = (uint32_t)((wm * 64 + mi * 16 + rA) * 128);
#pragma unroll
    for (int pr = 0; pr < 4; pr++)
        brow[pr] = (uint32_t)((wn * 64 + pr * 16 + rB) * 128) + STAGE_A;
#pragma unroll
    for (int ks = 0; ks < 4; ks++) {
        koffA[ks] = (uint32_t)((ks * 32 + cA) ^ (rowin << 4));
        koffB[ks] = (uint32_t)((ks * 32 + cB) ^ (rowin << 4));
    }

    issue_A(0, sb, m0, tid); issue_B(0, sb, n0, tid); CP_COMMIT();
    issue_A(1, sb, m0, tid); issue_B(1, sb, n0, tid); CP_COMMIT();

    for (int s = 0; s < NS; s++) {
        CP_WAIT1();
        __syncthreads();
        // Barrier proves mma(s-1) complete => buffer (s+2)%3 == (s-1)%3 safe.
        const uint32_t stg = sb + (uint32_t)((s % 3) * STAGE_BYTES);
#pragma unroll
        for (int ks = 0; ks < 4; ks++) {
            uint32_t af[4][4], bf[8][2];
#pragma unroll
            for (int mi = 0; mi < 4; mi++)
                ldmx4(af[mi], stg + arow[mi] + koffA[ks]);
#pragma unroll
            for (int pr = 0; pr < 4; pr++) {
                uint32_t r[4];
                ldmx4(r, stg + brow[pr] + koffB[ks]);
                bf[pr * 2][0]     = r[0];
                bf[pr * 2][1]     = r[1];
                bf[pr * 2 + 1][0] = r[2];
                bf[pr * 2 + 1][1] = r[3];
            }
            if (ks == 0) issue_A(s + 2, sb, m0, tid);
            if (ks == 1) { issue_B(s + 2, sb, n0, tid); CP_COMMIT(); }
#pragma unroll
            for (int mi = 0; mi < 4; mi++)
#pragma unroll
                for (int ni = 0; ni < 8; ni++)
                    mma16816(acc[mi * 8 + ni], af[mi], bf[ni]);
        }
    }

    // Epilogue: undo 2^12 W scaling.
    const int t4 = lane >> 2, tq = lane & 3;
#pragma unroll
    for (int mi = 0; mi < 4; mi++) {
        int r = m0 + wm * 64 + mi * 16 + t4;
#pragma unroll
        for (int ni = 0; ni < 8; ni++) {
            int c = n0 + wn * 64 + ni * 8 + tq * 2;
            float* a = acc[mi * 8 + ni];
            float2 v0 = make_float2(a[0] * INV_WSCALE, a[1] * INV_WSCALE);
            float2 v1 = make_float2(a[2] * INV_WSCALE, a[3] * INV_WSCALE);
            *reinterpret_cast<float2*>(OUT + (size_t)r * NFEAT + c) = v0;
            *reinterpret_cast<float2*>(OUT + (size_t)(r + 8) * NFEAT + c) = v1;
        }
    }
}

// ============================================================================
// Launch: fused prep/build, then GEMM (serial — overlap attempts lost twice).
// ============================================================================
extern "C" void kernel_launch(void* const* d_in, const int* in_sizes, int n_in,
                              void* d_out, int out_size) {
    const float* x = nullptr;
    const float* V = nullptr;
    const float* alpha = nullptr;
    for (int i = 0; i < n_in; i++) {
        if (in_sizes[i] == NFEAT)               alpha = (const float*)d_in[i];
        else if (in_sizes[i] == MROWS * NFEAT)  x     = (const float*)d_in[i];
        else                                    V     = (const float*)d_in[i];
    }
    float* out = (float*)d_out;

    cudaFuncSetAttribute(gemm_kernel, cudaFuncAttributeMaxDynamicSharedMemorySize, GEMM_SMEM);

    prep_build_kernel<<<3073, 256>>>(alpha, x, V);
    gemm_kernel<<<dim3(NFEAT / BN, MROWS / BM), 128, GEMM_SMEM>>>(out);
}